// round 14
// baseline (speedup 1.0000x reference)
#include <cuda_runtime.h>
#include <math.h>

#define LL 2048
#define EDGE_DIM 32
#define NODE_DIM 64
#define NTHREADS 256
#define NWARPS (NTHREADS / 32)

#define PARTS 4
#define JCHUNK (LL / PARTS)            // 512 j's per CTA
#define JPW (JCHUNK / NWARPS)          // 64 j's per warp
#define NSTEPS (JPW / 4)               // 16 steps, 4 rows per warp-step

#define LOG2E 1.4426950408889634f
#define LANE_SHIFT (-4.0f)             // x8 lanes => -32 in log2 units (softmax-invariant)

__device__ float4 g_part[LL * PARTS];  // per-(row,chunk) partial {s,vx,vy,vz}, 128 KB
__device__ float  g_mag[LL];           // per-row magnitude, written by part==0 CTAs

__device__ __forceinline__ float ex2f(float x) {
    float y;
    asm("ex2.approx.f32 %0, %1;" : "=f"(y) : "f"(x));
    return y;
}

__global__ __launch_bounds__(NTHREADS, 8)
void se3_main_kernel(const float* __restrict__ coords,
                     const float* __restrict__ nodef,
                     const float* __restrict__ pairf,
                     const float* __restrict__ w_attn,
                     const float* __restrict__ w_mag,
                     const float* __restrict__ b_mag)
{
    __shared__ float4 ud[NWARPS][JPW];   // per-warp {ux,uy,uz,d}, 8 KB total
    __shared__ float  red[NWARPS][4];

    const int tid  = threadIdx.x;
    const int i    = blockIdx.x;         // row
    const int part = blockIdx.y;         // column chunk
    const int lane = tid & 31;
    const int warp = tid >> 5;
    const int grp  = lane >> 3;          // 4 row-groups of 8 lanes
    const int j0   = part * JCHUNK;

    // this lane's 4 attention weights, pre-scaled by log2(e)
    const int wbase = (lane & 7) * 4;
    const float w0  = __ldg(&w_attn[wbase + 0]) * LOG2E;
    const float w1  = __ldg(&w_attn[wbase + 1]) * LOG2E;
    const float w2  = __ldg(&w_attn[wbase + 2]) * LOG2E;
    const float w3  = __ldg(&w_attn[wbase + 3]) * LOG2E;
    const float wdl = __ldg(&w_attn[EDGE_DIM]) * LOG2E;

    const float cix = __ldg(&coords[3*i+0]);
    const float ciy = __ldg(&coords[3*i+1]);
    const float ciz = __ldg(&coords[3*i+2]);

    // part==0 CTAs: warp 1 additionally computes the row magnitude (hidden latency)
    if (part == 0 && warp == 1) {
        float a = fmaf(__ldg(&nodef[(size_t)i * NODE_DIM + lane]),      __ldg(&w_mag[lane]),
                  __ldg(&nodef[(size_t)i * NODE_DIM + 32 + lane]) * __ldg(&w_mag[32 + lane]));
        #pragma unroll
        for (int o = 16; o > 0; o >>= 1) a += __shfl_xor_sync(0xFFFFFFFFu, a, o);
        if (lane == 0)
            g_mag[i] = tanhf(a + __ldg(&b_mag[0])) * 0.1f;
    }

    // WARP-LOCAL prologue: each warp fills only its own 64 ud entries (2/lane).
    // No cross-warp dependency => no __syncthreads before the stream loop.
    const int jwbase = j0 + warp * JPW;
    #pragma unroll
    for (int q = 0; q < JPW / 32; ++q) {
        const int idx = q * 32 + lane;
        const int j   = jwbase + idx;
        const float dx = cix - __ldg(&coords[3*j+0]);
        const float dy = ciy - __ldg(&coords[3*j+1]);
        const float dz = ciz - __ldg(&coords[3*j+2]);
        const float d2 = fmaf(dx, dx, fmaf(dy, dy, dz * dz));
        const float r  = rsqrtf(d2 + 1e-30f);   // j==i: u->0, d->0
        ud[warp][idx] = make_float4(dx * r, dy * r, dz * r, d2 * r);
    }
    __syncwarp();

    float s = 0.f, vx = 0.f, vy = 0.f, vz = 0.f;

    // pointer-bump addressing: warp starts at its first 4-row block, +32 float4/step
    const float4* p = reinterpret_cast<const float4*>(
        pairf + (size_t)i * LL * EDGE_DIM)
        + (size_t)jwbase * 8 + lane;
    const float4* uptr = &ud[warp][grp];

    #pragma unroll 8
    for (int k = 0; k < NSTEPS; ++k, p += 32, uptr += 4) {
        // coalesced: 32 lanes cover 4 consecutive rows; streaming (evict-first)
        const float4 t = __ldcs(p);

        // partial dot (pre-scaled log2 domain) with folded stability shift
        float dot = fmaf(t.x, w0, LANE_SHIFT);
        dot = fmaf(t.y, w1, dot);
        dot = fmaf(t.z, w2, dot);
        dot = fmaf(t.w, w3, dot);
        dot += __shfl_xor_sync(0xFFFFFFFFu, dot, 1);
        dot += __shfl_xor_sync(0xFFFFFFFFu, dot, 2);
        dot += __shfl_xor_sync(0xFFFFFFFFu, dot, 4);
        // all 8 lanes of a group hold the full dot for row j

        const float4 u = *uptr;
        const float  e = ex2f(fmaf(u.w, wdl, dot));
        s  += e;
        vx  = fmaf(e, u.x, vx);
        vy  = fmaf(e, u.y, vy);
        vz  = fmaf(e, u.z, vz);
    }

    // combine 4 groups (lanes within a group hold identical state): pure sums
    #pragma unroll
    for (int o = 8; o <= 16; o <<= 1) {
        s  += __shfl_xor_sync(0xFFFFFFFFu, s,  o);
        vx += __shfl_xor_sync(0xFFFFFFFFu, vx, o);
        vy += __shfl_xor_sync(0xFFFFFFFFu, vy, o);
        vz += __shfl_xor_sync(0xFFFFFFFFu, vz, o);
    }
    if (lane == 0) {
        red[warp][0] = s;  red[warp][1] = vx;
        red[warp][2] = vy; red[warp][3] = vz;
    }
    __syncthreads();

    if (warp == 0 && lane < NWARPS) {
        s  = red[lane][0]; vx = red[lane][1];
        vy = red[lane][2]; vz = red[lane][3];
        #pragma unroll
        for (int o = 4; o > 0; o >>= 1) {
            s  += __shfl_xor_sync(0x000000FFu, s,  o);
            vx += __shfl_xor_sync(0x000000FFu, vx, o);
            vy += __shfl_xor_sync(0x000000FFu, vy, o);
            vz += __shfl_xor_sync(0x000000FFu, vz, o);
        }
        if (lane == 0)
            g_part[i * PARTS + part] = make_float4(s, vx, vy, vz);
    }

    // signal PDL completion early (g_part/g_mag stores visible to the secondary
    // after its cudaGridDependencySynchronize)
    cudaTriggerProgrammaticLaunchCompletion();
}

// PDL secondary: trivial pre-sync work, then combine partials + apply magnitude.
__global__ __launch_bounds__(NTHREADS)
void se3_finalize_kernel(const float* __restrict__ coords,
                         float* __restrict__ out)
{
    const int lane = threadIdx.x & 31;
    const int warp = threadIdx.x >> 5;
    const int row  = blockIdx.x * NWARPS + warp;

    // g_part-independent: coords only
    const float c0 = __ldg(&coords[3*row+0]);
    const float c1 = __ldg(&coords[3*row+1]);
    const float c2 = __ldg(&coords[3*row+2]);

    cudaGridDependencySynchronize();

    float s = 0.f, vx = 0.f, vy = 0.f, vz = 0.f;
    if (lane < PARTS) {
        const float4 p = g_part[row * PARTS + lane];
        s = p.x; vx = p.y; vy = p.z; vz = p.w;
    }
    #pragma unroll
    for (int o = 1; o < PARTS; o <<= 1) {
        s  += __shfl_xor_sync(0xFFFFFFFFu, s,  o);
        vx += __shfl_xor_sync(0xFFFFFFFFu, vx, o);
        vy += __shfl_xor_sync(0xFFFFFFFFu, vy, o);
        vz += __shfl_xor_sync(0xFFFFFFFFu, vz, o);
    }

    if (lane == 0) {
        const float fac = g_mag[row] / s;
        out[3*row+0] = c0 + vx * fac;
        out[3*row+1] = c1 + vy * fac;
        out[3*row+2] = c2 + vz * fac;
    }
}

extern "C" void kernel_launch(void* const* d_in, const int* in_sizes, int n_in,
                              void* d_out, int out_size)
{
    const float* coords = (const float*)d_in[0];
    const float* nodef  = (const float*)d_in[1];
    const float* pairf  = (const float*)d_in[2];
    const float* w_attn = (const float*)d_in[3];
    // d_in[4] = b_attn : softmax-invariant, unused
    const float* w_mag  = (const float*)d_in[5];
    const float* b_mag  = (const float*)d_in[6];
    float* out = (float*)d_out;

    dim3 grid_main(LL, PARTS);
    se3_main_kernel<<<grid_main, NTHREADS>>>(coords, nodef, pairf, w_attn,
                                             w_mag, b_mag);

    // finalize with programmatic dependent launch: overlaps main's tail
    cudaLaunchConfig_t cfg = {};
    cfg.gridDim  = dim3(LL / NWARPS);
    cfg.blockDim = dim3(NTHREADS);
    cfg.dynamicSmemBytes = 0;
    cfg.stream = 0;
    cudaLaunchAttribute attrs[1];
    attrs[0].id = cudaLaunchAttributeProgrammaticStreamSerialization;
    attrs[0].val.programmaticStreamSerializationAllowed = 1;
    cfg.attrs = attrs;
    cfg.numAttrs = 1;
    cudaLaunchKernelEx(&cfg, se3_finalize_kernel, coords, out);
}